// round 1
// baseline (speedup 1.0000x reference)
#include <cuda_runtime.h>
#include <cuda_bf16.h>
#include <cstddef>

// Problem constants (from reference): N=50000, DEG=32, E=N*32, F=64, K=3, DIM=2, L=3
#define MAXN 50000
#define FDIM 64
#define KKER 3
#define KF   192   // K * F

// Scratch (device globals — no allocation allowed in kernel_launch)
__device__ float g_buf[(size_t)MAXN * KF];        // aggregated [N, K*F]
__device__ float h_bufA[(size_t)MAXN * FDIM];
__device__ float h_bufB[(size_t)MAXN * FDIM];

// ---------------------------------------------------------------------------
// Aggregation kernel: one warp per destination node.
//   g[i, k*64 + f] = sum_{e in [rowptr[i], rowptr[i+1])} w_k(e) * h[colind[e], f]
// w_k(e) = exp(-0.5 * sum_d (tanh(pseudo[e] @ pW + pb)_d - mu[k,d])^2 * is[k,d]^2)
// ---------------------------------------------------------------------------
__global__ __launch_bounds__(256)
void agg_kernel(const float* __restrict__ h,
                const float* __restrict__ pseudo,   // [E,2]
                const int*   __restrict__ rowptr,   // [N+1]
                const int*   __restrict__ colind,   // [E]
                const float* __restrict__ pW,       // [2,2] for this layer
                const float* __restrict__ pb,       // [2]
                const float* __restrict__ mu,       // [K,2]
                const float* __restrict__ isg,      // [K,2]
                float* __restrict__ g, int n)
{
    __shared__ float w0s[8][32], w1s[8][32], w2s[8][32];
    __shared__ int   ss[8][32];

    const int wid = threadIdx.x >> 5;
    const int lid = threadIdx.x & 31;
    const int node = blockIdx.x * 8 + wid;
    if (node >= n) return;

    const float W00 = pW[0], W01 = pW[1], W10 = pW[2], W11 = pW[3];
    const float b0 = pb[0], b1 = pb[1];
    const float m00 = mu[0], m01 = mu[1], m10 = mu[2], m11 = mu[3], m20 = mu[4], m21 = mu[5];
    const float s00 = isg[0]*isg[0], s01 = isg[1]*isg[1];
    const float s10 = isg[2]*isg[2], s11 = isg[3]*isg[3];
    const float s20 = isg[4]*isg[4], s21 = isg[5]*isg[5];

    const int e0 = rowptr[node], e1 = rowptr[node + 1];

    float a0x = 0.f, a0y = 0.f, a1x = 0.f, a1y = 0.f, a2x = 0.f, a2y = 0.f;
    const float2* __restrict__ ps2 = (const float2*)pseudo;

    for (int base = e0; base < e1; base += 32) {
        const int cnt = min(32, e1 - base);
        if (lid < cnt) {
            const int e = base + lid;
            float2 ps = __ldg(&ps2[e]);
            float u0 = tanhf(fmaf(ps.y, W10, fmaf(ps.x, W00, b0)));
            float u1 = tanhf(fmaf(ps.y, W11, fmaf(ps.x, W01, b1)));
            float d0, d1;
            d0 = u0 - m00; d1 = u1 - m01;
            w0s[wid][lid] = __expf(-0.5f * (d0*d0*s00 + d1*d1*s01));
            d0 = u0 - m10; d1 = u1 - m11;
            w1s[wid][lid] = __expf(-0.5f * (d0*d0*s10 + d1*d1*s11));
            d0 = u0 - m20; d1 = u1 - m21;
            w2s[wid][lid] = __expf(-0.5f * (d0*d0*s20 + d1*d1*s21));
            ss[wid][lid] = __ldg(&colind[e]);
        }
        __syncwarp();
        if (cnt == 32) {
            #pragma unroll 8
            for (int t = 0; t < 32; t++) {
                const float2 hv = __ldg((const float2*)(h + (size_t)ss[wid][t] * FDIM) + lid);
                const float w0 = w0s[wid][t], w1 = w1s[wid][t], w2 = w2s[wid][t];
                a0x = fmaf(w0, hv.x, a0x); a0y = fmaf(w0, hv.y, a0y);
                a1x = fmaf(w1, hv.x, a1x); a1y = fmaf(w1, hv.y, a1y);
                a2x = fmaf(w2, hv.x, a2x); a2y = fmaf(w2, hv.y, a2y);
            }
        } else {
            for (int t = 0; t < cnt; t++) {
                const float2 hv = __ldg((const float2*)(h + (size_t)ss[wid][t] * FDIM) + lid);
                const float w0 = w0s[wid][t], w1 = w1s[wid][t], w2 = w2s[wid][t];
                a0x = fmaf(w0, hv.x, a0x); a0y = fmaf(w0, hv.y, a0y);
                a1x = fmaf(w1, hv.x, a1x); a1y = fmaf(w1, hv.y, a1y);
                a2x = fmaf(w2, hv.x, a2x); a2y = fmaf(w2, hv.y, a2y);
            }
        }
        __syncwarp();
    }

    const size_t o = (size_t)node * KF;
    ((float2*)(g + o      ))[lid] = make_float2(a0x, a0y);
    ((float2*)(g + o +  64))[lid] = make_float2(a1x, a1y);
    ((float2*)(g + o + 128))[lid] = make_float2(a2x, a2y);
}

// ---------------------------------------------------------------------------
// GEMM kernel: out[i,f] = sum_{p=k*64+j} g[i,p] * fcW[j*192 + k*64 + f]
// Block tile 64 rows x 64 cols, thread tile 8 rows x 4 cols, 128 threads.
// Full weight (192x64 = 48KB) + g tile in dynamic shared.
// ---------------------------------------------------------------------------
#define GS_STRIDE 196     // 192 + 4 pad (not strictly needed, row-major broadcast reads)
#define GEMM_SMEM ((192*64 + 64*GS_STRIDE) * 4)

__global__ __launch_bounds__(128)
void gemm_kernel(const float* __restrict__ g,   // [n, 192]
                 const float* __restrict__ W,   // fc_W for this layer [64, 192]
                 float* __restrict__ out, int n)
{
    extern __shared__ float smem[];
    float* Ws = smem;                  // [192][64]
    float* gs = smem + 192 * 64;       // [64][GS_STRIDE]

    const int tid = threadIdx.x;
    // Load weights once: Ws[p][f] with p = k*64 + j  ->  W[j*192 + k*64 + f]
    for (int idx = tid; idx < 192 * 64; idx += 128) {
        const int p = idx >> 6, f = idx & 63;
        const int j = p & 63, k = p >> 6;
        Ws[idx] = __ldg(&W[j * 192 + k * 64 + f]);
    }

    const int tx = tid & 15;   // col group: cols tx*4 .. tx*4+3
    const int ty = tid >> 4;   // row group: rows ty*8 .. ty*8+7

    for (int r0 = blockIdx.x * 64; r0 < n; r0 += gridDim.x * 64) {
        __syncthreads();  // previous-iteration readers done (also covers Ws on iter 0 after load below sync)
        const int rows = min(64, n - r0);
        for (int idx = tid; idx < rows * 192; idx += 128) {
            const int r = idx / 192, p = idx - r * 192;
            gs[r * GS_STRIDE + p] = __ldg(&g[(size_t)(r0 + r) * 192 + p]);
        }
        __syncthreads();

        float acc[8][4];
        #pragma unroll
        for (int rr = 0; rr < 8; rr++)
            #pragma unroll
            for (int c = 0; c < 4; c++) acc[rr][c] = 0.f;

        #pragma unroll 2
        for (int p = 0; p < 192; p++) {
            const float4 w4 = *(const float4*)&Ws[p * 64 + tx * 4];
            #pragma unroll
            for (int rr = 0; rr < 8; rr++) {
                const float gv = gs[(ty * 8 + rr) * GS_STRIDE + p];
                acc[rr][0] = fmaf(gv, w4.x, acc[rr][0]);
                acc[rr][1] = fmaf(gv, w4.y, acc[rr][1]);
                acc[rr][2] = fmaf(gv, w4.z, acc[rr][2]);
                acc[rr][3] = fmaf(gv, w4.w, acc[rr][3]);
            }
        }

        #pragma unroll
        for (int rr = 0; rr < 8; rr++) {
            const int r = ty * 8 + rr;
            if (r < rows) {
                float4 o4 = make_float4(acc[rr][0], acc[rr][1], acc[rr][2], acc[rr][3]);
                *(float4*)&out[(size_t)(r0 + r) * FDIM + tx * 4] = o4;
            }
        }
    }
}

// ---------------------------------------------------------------------------
extern "C" void kernel_launch(void* const* d_in, const int* in_sizes, int n_in,
                              void* d_out, int out_size)
{
    const float* feat   = (const float*)d_in[0];
    const float* pseudo = (const float*)d_in[1];
    const int*   rowptr = (const int*)  d_in[2];
    const int*   colind = (const int*)  d_in[3];
    const float* projW  = (const float*)d_in[4];  // [L,2,2]
    const float* projb  = (const float*)d_in[5];  // [L,2]
    const float* fcW    = (const float*)d_in[6];  // [L,64,192]
    const float* mu     = (const float*)d_in[7];  // [L,3,2]
    const float* isg    = (const float*)d_in[8];  // [L,3,2]

    const int n  = in_sizes[0] / FDIM;
    const int nL = in_sizes[6] / (FDIM * KF);

    void *gp, *hap, *hbp;
    cudaGetSymbolAddress(&gp,  g_buf);
    cudaGetSymbolAddress(&hap, h_bufA);
    cudaGetSymbolAddress(&hbp, h_bufB);
    float* gbuf = (float*)gp;
    float* hbufs[2] = { (float*)hap, (float*)hbp };

    cudaFuncSetAttribute(gemm_kernel, cudaFuncAttributeMaxDynamicSharedMemorySize, GEMM_SMEM);

    const int aggGrid  = (n + 7) / 8;
    const int gemmGrid = (n + 63) / 64;

    const float* hin = feat;
    for (int i = 0; i < nL; i++) {
        float* hout = (i == nL - 1) ? (float*)d_out : hbufs[i & 1];
        agg_kernel<<<aggGrid, 256>>>(hin, pseudo, rowptr, colind,
                                     projW + i * 4, projb + i * 2,
                                     mu + i * 6, isg + i * 6,
                                     gbuf, n);
        gemm_kernel<<<gemmGrid, 128, GEMM_SMEM>>>(gbuf, fcW + i * (FDIM * KF), hout, n);
        hin = hout;
    }
}